// round 9
// baseline (speedup 1.0000x reference)
#include <cuda_runtime.h>
#include <cuda_bf16.h>
#include <cstdint>

#define NB 4
#define NT 4096
#define NE 1024
#define HS 64

// Scratch (static device arrays — no allocation)
__device__ float    g_q[NB * NT * HS];
__device__ uint32_t g_khp[NB * NT * 32];     // K hi, bf16x2 pairs along d
__device__ uint32_t g_klp[NB * NT * 32];     // K lo
__device__ uint32_t g_vthp[NB * HS * 2048];  // V^T hi, [b][d][t-pairs]
__device__ uint32_t g_vtlp[NB * HS * 2048];  // V^T lo
__device__ uint32_t g_whp[192 * 512];        // W split hi
__device__ uint32_t g_wlp[192 * 512];        // W split lo

// ---------------------------------------------------------------------------
__device__ __forceinline__ void split2(float a, float b, uint32_t& hi, uint32_t& lo) {
    __nv_bfloat162 h2 = __floats2bfloat162_rn(a, b);
    float2 hf = __bfloat1622float2(h2);
    __nv_bfloat162 l2 = __floats2bfloat162_rn(a - hf.x, b - hf.y);
    hi = *reinterpret_cast<uint32_t*>(&h2);
    lo = *reinterpret_cast<uint32_t*>(&l2);
}

__device__ __forceinline__ void mma16816(float* c, const uint32_t* a,
                                         uint32_t b0, uint32_t b1) {
    asm volatile(
        "mma.sync.aligned.m16n8k16.row.col.f32.bf16.bf16.f32 "
        "{%0,%1,%2,%3}, {%4,%5,%6,%7}, {%8,%9}, {%0,%1,%2,%3};"
        : "+f"(c[0]), "+f"(c[1]), "+f"(c[2]), "+f"(c[3])
        : "r"(a[0]), "r"(a[1]), "r"(a[2]), "r"(a[3]), "r"(b0), "r"(b1));
}

__device__ __forceinline__ void ldsm4(uint32_t* r, uint32_t addr) {
    asm volatile("ldmatrix.sync.aligned.m8n8.x4.shared.b16 {%0,%1,%2,%3}, [%4];"
                 : "=r"(r[0]), "=r"(r[1]), "=r"(r[2]), "=r"(r[3]) : "r"(addr));
}

__device__ __forceinline__ uint32_t smem_u32(const void* p) {
    uint32_t a;
    asm("{ .reg .u64 t; cvta.to.shared.u64 t, %1; cvt.u32.u64 %0, t; }"
        : "=r"(a) : "l"(p));
    return a;
}

__device__ __forceinline__ void cp16(uint32_t s, const void* g) {
    asm volatile("cp.async.cg.shared.global [%0], [%1], 16;"
                 :: "r"(s), "l"(__cvta_generic_to_global(g)) : "memory");
}

#define ROWB 144   // K/Q/W smem row stride (conflict-free: 36 words ≡ 4 mod 32)
#define VRB  272   // V^T smem row stride (68 words ≡ 4 mod 32)

// ===========================================================================
// Stage 0: one-time W split
// ===========================================================================
__global__ __launch_bounds__(256) void wprep(
    const float* __restrict__ Wq,
    const float* __restrict__ Wk,
    const float* __restrict__ Wv)
{
    const int row = blockIdx.x;
    const float* W = (row < 64) ? Wq : ((row < 128) ? Wk : Wv);
    const int r = row & 63;
    #pragma unroll
    for (int i = 0; i < 2; i++) {
        const int p = threadIdx.x + i * 256;
        float2 v = *(const float2*)&W[(size_t)r * NE + 2 * p];
        uint32_t hi, lo;
        split2(v.x, v.y, hi, lo);
        g_whp[row * 512 + p] = hi;
        g_wlp[row * 512 + p] = lo;
    }
}

// ===========================================================================
// Stage 1: fused QKV projection. 3-stage W ring, 1 barrier per chunk.
// ===========================================================================
#define QKV_XH 0
#define QKV_XL 18432
#define QKV_WBASE 36864
#define QKV_WSTG 55296          // Wh 27648 | Wl 27648
#define QKV_SMEM (QKV_WBASE + 3 * QKV_WSTG)   // 202752

__global__ __launch_bounds__(256, 1) void qkv_mma(
    const float* __restrict__ x,
    const float* __restrict__ Wq,
    const float* __restrict__ Wk,
    const float* __restrict__ Wv)
{
    extern __shared__ __align__(16) char sm[];
    const uint32_t sb = smem_u32(sm);
    char* Xh = sm + QKV_XH;
    char* Xl = sm + QKV_XL;

    const int tid = threadIdx.x;
    const int wid = tid >> 5;
    const int lane = tid & 31;
    const int g  = lane >> 2;
    const int t3 = lane & 3;
    const int m8 = lane >> 3;
    const int r8 = lane & 7;
    const int rowblk = blockIdx.x * 128;

    const uint32_t lmw = (uint32_t)(((m8 >> 1) * 8 + r8) * ROWB + (m8 & 1) * 16);

    const int xrow = tid >> 1;
    const int xc0  = (tid & 1) * 32;
    const int xob  = xrow * ROWB + xc0 * 2;

    float c[24][4];
    #pragma unroll
    for (int nt = 0; nt < 24; nt++)
        #pragma unroll
        for (int i = 0; i < 4; i++) c[nt][i] = 0.f;

    // X chunk 0 into regs
    float4 xr[8];
    {
        const float4* xsrc = (const float4*)&x[(size_t)(rowblk + xrow) * NE + xc0];
        #pragma unroll
        for (int i = 0; i < 8; i++) xr[i] = xsrc[i];
    }

    // prefetch W chunks 0 and 1
    #pragma unroll
    for (int pc = 0; pc < 2; pc++) {
        const uint32_t wst = sb + QKV_WBASE + pc * QKV_WSTG;
        #pragma unroll
        for (int i = 0; i < 6; i++) {
            const int idx = tid + i * 256;
            const int row = idx >> 3;
            const int off = (idx & 7) * 16;
            cp16(wst + row * ROWB + off,         (const char*)g_whp + row * 2048 + pc * 128 + off);
            cp16(wst + 27648 + row * ROWB + off, (const char*)g_wlp + row * 2048 + pc * 128 + off);
        }
        asm volatile("cp.async.commit_group;" ::: "memory");
    }

    int stg = 0;   // stage of current chunk
    for (int kci = 0; kci < 16; kci++) {
        if (kci < 15)
            asm volatile("cp.async.wait_group 1;" ::: "memory");
        else
            asm volatile("cp.async.wait_group 0;" ::: "memory");
        __syncthreads();   // visibility of stage stg + drain of stage (stg+2)%3 readers

        // prefetch chunk kci+2 into stage (stg+2)%3
        if (kci + 2 < 16) {
            const int ps = stg + 2 >= 3 ? stg - 1 : stg + 2;
            const uint32_t wst = sb + QKV_WBASE + ps * QKV_WSTG;
            const int kb2 = (kci + 2) * 128;
            #pragma unroll
            for (int i = 0; i < 6; i++) {
                const int idx = tid + i * 256;
                const int row = idx >> 3;
                const int off = (idx & 7) * 16;
                cp16(wst + row * ROWB + off,         (const char*)g_whp + row * 2048 + kb2 + off);
                cp16(wst + 27648 + row * ROWB + off, (const char*)g_wlp + row * 2048 + kb2 + off);
            }
            asm volatile("cp.async.commit_group;" ::: "memory");
        }

        // split current X regs into warp-local smem
        {
            uint32_t hp[16], lp[16];
            #pragma unroll
            for (int i = 0; i < 8; i++) {
                split2(xr[i].x, xr[i].y, hp[2*i],   lp[2*i]);
                split2(xr[i].z, xr[i].w, hp[2*i+1], lp[2*i+1]);
            }
            #pragma unroll
            for (int i = 0; i < 4; i++) {
                *(uint4*)(Xh + xob + 16*i) = make_uint4(hp[4*i], hp[4*i+1], hp[4*i+2], hp[4*i+3]);
                *(uint4*)(Xl + xob + 16*i) = make_uint4(lp[4*i], lp[4*i+1], lp[4*i+2], lp[4*i+3]);
            }
        }
        __syncwarp();

        if (kci + 1 < 16) {
            const float4* xsrc = (const float4*)&x[(size_t)(rowblk + xrow) * NE + (kci + 1) * 64 + xc0];
            #pragma unroll
            for (int i = 0; i < 8; i++) xr[i] = xsrc[i];
        }

        const uint32_t whb = sb + QKV_WBASE + stg * QKV_WSTG;
        const uint32_t wlb = whb + 27648;

        const int rb = (wid * 16 + g) * ROWB;
        #pragma unroll
        for (int ks = 0; ks < 4; ks++) {
            const int colb = ks * 32 + t3 * 4;
            uint32_t ah[4], al[4];
            ah[0] = *(uint32_t*)(Xh + rb + colb);
            ah[1] = *(uint32_t*)(Xh + rb + 8*ROWB + colb);
            ah[2] = *(uint32_t*)(Xh + rb + colb + 16);
            ah[3] = *(uint32_t*)(Xh + rb + 8*ROWB + colb + 16);
            al[0] = *(uint32_t*)(Xl + rb + colb);
            al[1] = *(uint32_t*)(Xl + rb + 8*ROWB + colb);
            al[2] = *(uint32_t*)(Xl + rb + colb + 16);
            al[3] = *(uint32_t*)(Xl + rb + 8*ROWB + colb + 16);
            #pragma unroll
            for (int ntp = 0; ntp < 12; ntp++) {
                uint32_t wh4[4], wl4[4];
                ldsm4(wh4, whb + lmw + ntp * (16 * ROWB) + ks * 32);
                ldsm4(wl4, wlb + lmw + ntp * (16 * ROWB) + ks * 32);
                mma16816(c[2*ntp],   ah, wh4[0], wh4[1]);
                mma16816(c[2*ntp],   ah, wl4[0], wl4[1]);
                mma16816(c[2*ntp],   al, wh4[0], wh4[1]);
                mma16816(c[2*ntp+1], ah, wh4[2], wh4[3]);
                mma16816(c[2*ntp+1], ah, wl4[2], wl4[3]);
                mma16816(c[2*ntp+1], al, wh4[2], wh4[3]);
            }
        }
        stg = (stg + 1 == 3) ? 0 : stg + 1;
    }

    const int r0 = rowblk + wid * 16 + g;
    #pragma unroll
    for (int nt = 0; nt < 8; nt++) {
        const int col = nt * 8 + t3 * 2;
        *(float2*)&g_q[(size_t)r0 * HS + col]       = make_float2(c[nt][0], c[nt][1]);
        *(float2*)&g_q[(size_t)(r0 + 8) * HS + col] = make_float2(c[nt][2], c[nt][3]);
    }
    #pragma unroll
    for (int nt = 8; nt < 16; nt++) {
        const int pidx = (nt - 8) * 4 + t3;
        uint32_t hi, lo;
        split2(c[nt][0], c[nt][1], hi, lo);
        g_khp[(size_t)r0 * 32 + pidx] = hi;
        g_klp[(size_t)r0 * 32 + pidx] = lo;
        split2(c[nt][2], c[nt][3], hi, lo);
        g_khp[(size_t)(r0 + 8) * 32 + pidx] = hi;
        g_klp[(size_t)(r0 + 8) * 32 + pidx] = lo;
    }

    __syncthreads();
    float* Vs = (float*)sm;       // [64][132] — X area dead
    const int rloc = wid * 16 + g;
    #pragma unroll
    for (int nt = 16; nt < 24; nt++) {
        const int n = nt * 8 + t3 * 2 - 128;
        Vs[n * 132 + rloc]           = c[nt][0];
        Vs[(n + 1) * 132 + rloc]     = c[nt][1];
        Vs[n * 132 + rloc + 8]       = c[nt][2];
        Vs[(n + 1) * 132 + rloc + 8] = c[nt][3];
    }
    __syncthreads();
    {
        const int d  = tid >> 2;
        const int cc = (tid & 3) * 32;
        const int bb = rowblk >> 12;
        const int t0 = rowblk & (NT - 1);
        uint32_t* dh = &g_vthp[((size_t)(bb * HS + d)) * 2048 + (t0 + cc) / 2];
        uint32_t* dl = &g_vtlp[((size_t)(bb * HS + d)) * 2048 + (t0 + cc) / 2];
        #pragma unroll
        for (int i = 0; i < 8; i++) {
            float4 v = *(float4*)&Vs[d * 132 + cc + 4*i];
            uint32_t h0, l0, h1, l1;
            split2(v.x, v.y, h0, l0);
            split2(v.z, v.w, h1, l1);
            dh[2*i] = h0;  dh[2*i+1] = h1;
            dl[2*i] = l0;  dl[2*i+1] = l1;
        }
    }
}

// ===========================================================================
// Stage 2: causal flash attention. 128-key kv tiles, 3-stage ring, 2 syncs/iter.
// Warps 0-3 keys 0-63, warps 4-7 keys 64-127 of each tile; 16 rows/warp.
// ===========================================================================
#define SKH 0
#define SKL 18432
#define SVH 36864
#define SVL 54272
#define ATSTG 71680
#define AT_MSO (3 * ATSTG)          // 215040, float2[2][64]
#define AT_SMEM (AT_MSO + 1024)     // 216064
// Q staged inside stage 2's slot (consumed into regs before tile-2 prefetch)
#define AT_QHO (2 * ATSTG)
#define AT_QLO (2 * ATSTG + 9216)
#define OEXW 66

__global__ __launch_bounds__(256, 1) void attn3(float* __restrict__ o)
{
    extern __shared__ __align__(16) char sm[];
    const uint32_t sb = smem_u32(sm);
    const int tid  = threadIdx.x;
    const int wid  = tid >> 5;
    const int lane = tid & 31;
    const int g    = lane >> 2;
    const int t3   = lane & 3;
    const int wq   = wid & 3;
    const int side = wid >> 2;
    const int b    = blockIdx.y;

    const int m8 = lane >> 3;
    const int r8 = lane & 7;
    const uint32_t lmk = (uint32_t)((side * 64 + (m8 >> 1) * 8 + r8) * ROWB + (m8 & 1) * 16);
    const uint32_t lmv = (uint32_t)(((m8 >> 1) * 8 + r8) * VRB + (m8 & 1) * 16 + side * 128);

    const char* khg = (const char*)g_khp + (size_t)b * NT * 128;
    const char* klg = (const char*)g_klp + (size_t)b * NT * 128;
    const char* vhg = (const char*)g_vthp + (size_t)b * HS * 8192;
    const char* vlg = (const char*)g_vtlp + (size_t)b * HS * 8192;

    for (int half = 0; half < 2; half++) {
        const int qt = half ? (63 - (int)blockIdx.x) : (int)blockIdx.x;
        const int nkt = (qt + 2) >> 1;          // 128-key tiles
        const int qrow = b * NT + qt * 64;

        __syncthreads();   // prior half fully done (epilogue reads, cp drained)

        // ---- stage Q (scaled 1/8, split) into stage-2 slot ----
        {
            const int r  = tid >> 2;
            const int c0 = (tid & 3) * 16;
            const float4* src = (const float4*)&g_q[(size_t)(qrow + r) * HS + c0];
            uint32_t hp[8], lp[8];
            #pragma unroll
            for (int i = 0; i < 4; i++) {
                float4 v = src[i];
                split2(v.x * 0.125f, v.y * 0.125f, hp[2*i],   lp[2*i]);
                split2(v.z * 0.125f, v.w * 0.125f, hp[2*i+1], lp[2*i+1]);
            }
            const int ob = r * ROWB + c0 * 2;
            *(uint4*)(sm + AT_QHO + ob)      = make_uint4(hp[0], hp[1], hp[2], hp[3]);
            *(uint4*)(sm + AT_QHO + ob + 16) = make_uint4(hp[4], hp[5], hp[6], hp[7]);
            *(uint4*)(sm + AT_QLO + ob)      = make_uint4(lp[0], lp[1], lp[2], lp[3]);
            *(uint4*)(sm + AT_QLO + ob + 16) = make_uint4(lp[4], lp[5], lp[6], lp[7]);
        }
        __syncthreads();

        // ---- preload Q fragments ----
        uint32_t qh[4][4], ql[4][4];
        {
            const int rb = (wq * 16 + g) * ROWB;
            #pragma unroll
            for (int ks = 0; ks < 4; ks++) {
                const int colb = ks * 32 + t3 * 4;
                qh[ks][0] = *(uint32_t*)(sm + AT_QHO + rb + colb);
                qh[ks][1] = *(uint32_t*)(sm + AT_QHO + rb + 8*ROWB + colb);
                qh[ks][2] = *(uint32_t*)(sm + AT_QHO + rb + colb + 16);
                qh[ks][3] = *(uint32_t*)(sm + AT_QHO + rb + 8*ROWB + colb + 16);
                ql[ks][0] = *(uint32_t*)(sm + AT_QLO + rb + colb);
                ql[ks][1] = *(uint32_t*)(sm + AT_QLO + rb + 8*ROWB + colb);
                ql[ks][2] = *(uint32_t*)(sm + AT_QLO + rb + colb + 16);
                ql[ks][3] = *(uint32_t*)(sm + AT_QLO + rb + 8*ROWB + colb + 16);
            }
        }
        __syncthreads();   // Q fragments consumed before tile-2 prefetch may overwrite

        float oacc[8][4];
        #pragma unroll
        for (int nt = 0; nt < 8; nt++)
            #pragma unroll
            for (int i = 0; i < 4; i++) oacc[nt][i] = 0.f;
        float mi0 = -1e30f, mi1 = -1e30f, li0 = 0.f, li1 = 0.f;

        // ---- prefetch tiles 0 and (maybe) 1 ----
        #pragma unroll 1
        for (int pt = 0; pt < 2; pt++) {
            if (pt < nkt) {
                const uint32_t so = sb + pt * ATSTG;
                #pragma unroll
                for (int i = 0; i < 4; i++) {
                    const int cidx = tid + i * 256;      // 0..1023
                    const int kr = cidx >> 3, ko = (cidx & 7) * 16;
                    cp16(so + SKH + kr * ROWB + ko, khg + (size_t)(pt * 128 + kr) * 128 + ko);
                    cp16(so + SKL + kr * ROWB + ko, klg + (size_t)(pt * 128 + kr) * 128 + ko);
                    const int d = cidx >> 4, vo_ = (cidx & 15) * 16;
                    cp16(so + SVH + d * VRB + vo_, vhg + (size_t)d * 8192 + pt * 256 + vo_);
                    cp16(so + SVL + d * VRB + vo_, vlg + (size_t)d * 8192 + pt * 256 + vo_);
                }
                asm volatile("cp.async.commit_group;" ::: "memory");
            }
        }

        int stg = 0;
        for (int kt = 0; kt < nkt; kt++) {
            if (kt + 1 < nkt)
                asm volatile("cp.async.wait_group 1;" ::: "memory");
            else
                asm volatile("cp.async.wait_group 0;" ::: "memory");
            __syncthreads();   // sync(A): stage visibility + drain of (stg+2)%3 readers

            // prefetch tile kt+2 into stage (stg+2)%3
            if (kt + 2 < nkt) {
                const int ps = stg + 2 >= 3 ? stg - 1 : stg + 2;
                const uint32_t so = sb + ps * ATSTG;
                const int t2 = kt + 2;
                #pragma unroll
                for (int i = 0; i < 4; i++) {
                    const int cidx = tid + i * 256;
                    const int kr = cidx >> 3, ko = (cidx & 7) * 16;
                    cp16(so + SKH + kr * ROWB + ko, khg + (size_t)(t2 * 128 + kr) * 128 + ko);
                    cp16(so + SKL + kr * ROWB + ko, klg + (size_t)(t2 * 128 + kr) * 128 + ko);
                    const int d = cidx >> 4, vo_ = (cidx & 15) * 16;
                    cp16(so + SVH + d * VRB + vo_, vhg + (size_t)d * 8192 + t2 * 256 + vo_);
                    cp16(so + SVL + d * VRB + vo_, vlg + (size_t)d * 8192 + t2 * 256 + vo_);
                }
                asm volatile("cp.async.commit_group;" ::: "memory");
            }

            const uint32_t khb = sb + stg * ATSTG + SKH;
            const uint32_t klb = sb + stg * ATSTG + SKL;
            const uint32_t vhb = sb + stg * ATSTG + SVH;
            const uint32_t vlb = sb + stg * ATSTG + SVL;

            // ---- S = Q K^T over warp's 64 keys ----
            float s[8][4];
            #pragma unroll
            for (int nt = 0; nt < 8; nt++)
                #pragma unroll
                for (int i = 0; i < 4; i++) s[nt][i] = 0.f;
            #pragma unroll
            for (int ks = 0; ks < 4; ks++) {
                #pragma unroll
                for (int kb = 0; kb < 4; kb++) {
                    uint32_t h4[4], l4[4];
                    ldsm4(h4, khb + lmk + kb * (16 * ROWB) + ks * 32);
                    ldsm4(l4, klb + lmk + kb * (16 * ROWB) + ks * 32);
                    mma16816(s[2*kb],   qh[ks], h4[0], h4[1]);
                    mma16816(s[2*kb],   qh[ks], l4[0], l4[1]);
                    mma16816(s[2*kb],   ql[ks], h4[0], h4[1]);
                    mma16816(s[2*kb+1], qh[ks], h4[2], h4[3]);
                    mma16816(s[2*kb+1], qh[ks], l4[2], l4[3]);
                    mma16816(s[2*kb+1], ql[ks], h4[2], h4[3]);
                }
            }

            // ---- causal mask (last tile only) ----
            if (kt == nkt - 1) {
                const int lr0 = qt * 64 + wq * 16 + g;
                #pragma unroll
                for (int nt = 0; nt < 8; nt++) {
                    const int kc = kt * 128 + side * 64 + nt * 8 + t3 * 2;
                    if (kc > lr0)         s[nt][0] = -1e30f;
                    if (kc + 1 > lr0)     s[nt][1] = -1e30f;
                    if (kc > lr0 + 8)     s[nt][2] = -1e30f;
                    if (kc + 1 > lr0 + 8) s[nt][3] = -1e30f;
                }
            }

            // ---- partial softmax over warp's 64 cols ----
            float m0 = -1e30f, m1 = -1e30f;
            #pragma unroll
            for (int nt = 0; nt < 8; nt++) {
                m0 = fmaxf(m0, fmaxf(s[nt][0], s[nt][1]));
                m1 = fmaxf(m1, fmaxf(s[nt][2], s[nt][3]));
            }
            m0 = fmaxf(m0, __shfl_xor_sync(0xffffffffu, m0, 1));
            m0 = fmaxf(m0, __shfl_xor_sync(0xffffffffu, m0, 2));
            m1 = fmaxf(m1, __shfl_xor_sync(0xffffffffu, m1, 1));
            m1 = fmaxf(m1, __shfl_xor_sync(0xffffffffu, m1, 2));

            float sum0 = 0.f, sum1 = 0.f;
            #pragma unroll
            for (int nt = 0; nt < 8; nt++) {
                s[nt][0] = __expf(s[nt][0] - m0);
                s[nt][1] = __expf(s[nt][1] - m0);
                s[nt][2] = __expf(s[nt][2] - m1);
                s[nt][3] = __expf(s[nt][3] - m1);
                sum0 += s[nt][0] + s[nt][1];
                sum1 += s[nt][2] + s[nt][3];
            }
            sum0 += __shfl_xor_sync(0xffffffffu, sum0, 1);
            sum0 += __shfl_xor_sync(0xffffffffu, sum0, 2);
            sum1 += __shfl_xor_sync(0xffffffffu, sum1, 1);
            sum1 += __shfl_xor_sync(0xffffffffu, sum1, 2);

            if (t3 == 0) {
                *(float2*)(sm + AT_MSO + (side * 64 + wq * 16 + g) * 8)     = make_float2(m0, sum0);
                *(float2*)(sm + AT_MSO + (side * 64 + wq * 16 + g + 8) * 8) = make_float2(m1, sum1);
            }
            __syncthreads();   // sync(B)
            const float2 ot0 = *(float2*)(sm + AT_MSO + ((1 - side) * 64 + wq * 16 + g) * 8);
            const float2 ot1 = *(float2*)(sm + AT_MSO + ((1 - side) * 64 + wq * 16 + g + 8) * 8);

            const float mn0 = fmaxf(mi0, fmaxf(m0, ot0.x));
            const float mn1 = fmaxf(mi1, fmaxf(m1, ot1.x));
            const float fo0 = __expf(m0 - mn0), fo1 = __expf(m1 - mn1);
            const float corr0 = __expf(mi0 - mn0), corr1 = __expf(mi1 - mn1);
            li0 = li0 * corr0 + sum0 * fo0 + ot0.y * __expf(ot0.x - mn0);
            li1 = li1 * corr1 + sum1 * fo1 + ot1.y * __expf(ot1.x - mn1);
            mi0 = mn0;  mi1 = mn1;

            #pragma unroll
            for (int nt = 0; nt < 8; nt++) {
                s[nt][0] *= fo0;  s[nt][1] *= fo0;
                s[nt][2] *= fo1;  s[nt][3] *= fo1;
            }
            #pragma unroll
            for (int nt = 0; nt < 8; nt++) {
                oacc[nt][0] *= corr0;  oacc[nt][1] *= corr0;
                oacc[nt][2] *= corr1;  oacc[nt][3] *= corr1;
            }

            // ---- O += P V (4 ksteps of 16 keys) ----
            #pragma unroll
            for (int kk = 0; kk < 4; kk++) {
                uint32_t pah[4], pal[4];
                split2(s[2*kk][0],   s[2*kk][1],   pah[0], pal[0]);
                split2(s[2*kk][2],   s[2*kk][3],   pah[1], pal[1]);
                split2(s[2*kk+1][0], s[2*kk+1][1], pah[2], pal[2]);
                split2(s[2*kk+1][2], s[2*kk+1][3], pah[3], pal[3]);
                #pragma unroll
                for (int dt = 0; dt < 4; dt++) {
                    uint32_t vh4[4], vl4[4];
                    ldsm4(vh4, vhb + dt * (16 * VRB) + lmv + kk * 32);
                    ldsm4(vl4, vlb + dt * (16 * VRB) + lmv + kk * 32);
                    mma16816(oacc[2*dt],   pah, vh4[0], vh4[1]);
                    mma16816(oacc[2*dt],   pah, vl4[0], vl4[1]);
                    mma16816(oacc[2*dt],   pal, vh4[0], vh4[1]);
                    mma16816(oacc[2*dt+1], pah, vh4[2], vh4[3]);
                    mma16816(oacc[2*dt+1], pah, vl4[2], vl4[3]);
                    mma16816(oacc[2*dt+1], pal, vh4[2], vh4[3]);
                }
            }
            stg = (stg + 1 == 3) ? 0 : stg + 1;
        }

        // ---- epilogue: merge O partials across side pairs ----
        __syncthreads();
        float* Oex = (float*)sm;   // stage 0 area, pipeline drained
        if (side == 1) {
            #pragma unroll
            for (int nt = 0; nt < 8; nt++) {
                const int col = nt * 8 + t3 * 2;
                Oex[(wq*16 + g) * OEXW + col]         = oacc[nt][0];
                Oex[(wq*16 + g) * OEXW + col + 1]     = oacc[nt][1];
                Oex[(wq*16 + g + 8) * OEXW + col]     = oacc[nt][2];
                Oex[(wq*16 + g + 8) * OEXW + col + 1] = oacc[nt][3];
            }
        }
        __syncthreads();
        if (side == 0) {
            const float inv0 = 1.0f / li0;
            const float inv1 = 1.0f / li1;
            const int rowA = qrow + wq * 16 + g;
            #pragma unroll
            for (int nt = 0; nt < 8; nt++) {
                const int col = nt * 8 + t3 * 2;
                float a0 = (oacc[nt][0] + Oex[(wq*16 + g) * OEXW + col])     * inv0;
                float a1 = (oacc[nt][1] + Oex[(wq*16 + g) * OEXW + col + 1]) * inv0;
                float a2 = (oacc[nt][2] + Oex[(wq*16 + g + 8) * OEXW + col])     * inv1;
                float a3 = (oacc[nt][3] + Oex[(wq*16 + g + 8) * OEXW + col + 1]) * inv1;
                *(float2*)&o[(size_t)rowA * HS + col]       = make_float2(a0, a1);
                *(float2*)&o[(size_t)(rowA + 8) * HS + col] = make_float2(a2, a3);
            }
        }
    }
}

// ===========================================================================
extern "C" void kernel_launch(void* const* d_in, const int* in_sizes, int n_in,
                              void* d_out, int out_size)
{
    const float* x  = (const float*)d_in[0];
    const float* Wq = (const float*)d_in[1];
    const float* Wk = (const float*)d_in[2];
    const float* Wv = (const float*)d_in[3];
    float* out = (float*)d_out;
    (void)in_sizes; (void)n_in; (void)out_size;

    wprep<<<192, 256>>>(Wq, Wk, Wv);

    cudaFuncSetAttribute(qkv_mma, cudaFuncAttributeMaxDynamicSharedMemorySize,
                         QKV_SMEM);
    qkv_mma<<<128, 256, QKV_SMEM>>>(x, Wq, Wk, Wv);

    cudaFuncSetAttribute(attn3, cudaFuncAttributeMaxDynamicSharedMemorySize,
                         AT_SMEM);
    attn3<<<dim3(32, NB), 256, AT_SMEM>>>(out);
}

// round 11
// speedup vs baseline: 1.4117x; 1.4117x over previous
#include <cuda_runtime.h>
#include <cuda_bf16.h>
#include <cstdint>

#define NB 4
#define NT 4096
#define NE 1024
#define HS 64

// Scratch (static device arrays — no allocation)
__device__ float    g_q[NB * NT * HS];
__device__ uint32_t g_khp[NB * NT * 32];     // K hi, bf16x2 pairs along d
__device__ uint32_t g_klp[NB * NT * 32];     // K lo
__device__ uint32_t g_vthp[NB * HS * 2048];  // V^T hi, [b][d][t-pairs]
__device__ uint32_t g_vtlp[NB * HS * 2048];  // V^T lo
__device__ uint32_t g_whp[192 * 512];        // W split hi
__device__ uint32_t g_wlp[192 * 512];        // W split lo

// ---------------------------------------------------------------------------
__device__ __forceinline__ void split2(float a, float b, uint32_t& hi, uint32_t& lo) {
    __nv_bfloat162 h2 = __floats2bfloat162_rn(a, b);
    float2 hf = __bfloat1622float2(h2);
    __nv_bfloat162 l2 = __floats2bfloat162_rn(a - hf.x, b - hf.y);
    hi = *reinterpret_cast<uint32_t*>(&h2);
    lo = *reinterpret_cast<uint32_t*>(&l2);
}

__device__ __forceinline__ void mma16816(float* c, const uint32_t* a,
                                         uint32_t b0, uint32_t b1) {
    asm volatile(
        "mma.sync.aligned.m16n8k16.row.col.f32.bf16.bf16.f32 "
        "{%0,%1,%2,%3}, {%4,%5,%6,%7}, {%8,%9}, {%0,%1,%2,%3};"
        : "+f"(c[0]), "+f"(c[1]), "+f"(c[2]), "+f"(c[3])
        : "r"(a[0]), "r"(a[1]), "r"(a[2]), "r"(a[3]), "r"(b0), "r"(b1));
}

__device__ __forceinline__ void ldsm4(uint32_t* r, uint32_t addr) {
    asm volatile("ldmatrix.sync.aligned.m8n8.x4.shared.b16 {%0,%1,%2,%3}, [%4];"
                 : "=r"(r[0]), "=r"(r[1]), "=r"(r[2]), "=r"(r[3]) : "r"(addr));
}

__device__ __forceinline__ uint32_t smem_u32(const void* p) {
    uint32_t a;
    asm("{ .reg .u64 t; cvta.to.shared.u64 t, %1; cvt.u32.u64 %0, t; }"
        : "=r"(a) : "l"(p));
    return a;
}

__device__ __forceinline__ void cp16(uint32_t s, const void* g) {
    asm volatile("cp.async.cg.shared.global [%0], [%1], 16;"
                 :: "r"(s), "l"(__cvta_generic_to_global(g)) : "memory");
}

#define ROWB 144   // padded smem row stride — conflict-free ldmatrix

// ===========================================================================
// Stage 0: one-time W split
// ===========================================================================
__global__ __launch_bounds__(256) void wprep(
    const float* __restrict__ Wq,
    const float* __restrict__ Wk,
    const float* __restrict__ Wv)
{
    const int row = blockIdx.x;
    const float* W = (row < 64) ? Wq : ((row < 128) ? Wk : Wv);
    const int r = row & 63;
    #pragma unroll
    for (int i = 0; i < 2; i++) {
        const int p = threadIdx.x + i * 256;
        float2 v = *(const float2*)&W[(size_t)r * NE + 2 * p];
        uint32_t hi, lo;
        split2(v.x, v.y, hi, lo);
        g_whp[row * 512 + p] = hi;
        g_wlp[row * 512 + p] = lo;
    }
}

// ===========================================================================
// Stage 1: fused QKV projection. 3-stage W ring, 1 barrier per chunk.
// ===========================================================================
#define QKV_XH 0
#define QKV_XL 18432
#define QKV_WBASE 36864
#define QKV_WSTG 55296
#define QKV_SMEM (QKV_WBASE + 3 * QKV_WSTG)   // 202752

__global__ __launch_bounds__(256, 1) void qkv_mma(
    const float* __restrict__ x,
    const float* __restrict__ Wq,
    const float* __restrict__ Wk,
    const float* __restrict__ Wv)
{
    extern __shared__ __align__(16) char sm[];
    const uint32_t sb = smem_u32(sm);
    char* Xh = sm + QKV_XH;
    char* Xl = sm + QKV_XL;

    const int tid = threadIdx.x;
    const int wid = tid >> 5;
    const int lane = tid & 31;
    const int g  = lane >> 2;
    const int t3 = lane & 3;
    const int m8 = lane >> 3;
    const int r8 = lane & 7;
    const int rowblk = blockIdx.x * 128;

    const uint32_t lmw = (uint32_t)(((m8 >> 1) * 8 + r8) * ROWB + (m8 & 1) * 16);

    const int xrow = tid >> 1;
    const int xc0  = (tid & 1) * 32;
    const int xob  = xrow * ROWB + xc0 * 2;

    float c[24][4];
    #pragma unroll
    for (int nt = 0; nt < 24; nt++)
        #pragma unroll
        for (int i = 0; i < 4; i++) c[nt][i] = 0.f;

    float4 xr[8];
    {
        const float4* xsrc = (const float4*)&x[(size_t)(rowblk + xrow) * NE + xc0];
        #pragma unroll
        for (int i = 0; i < 8; i++) xr[i] = xsrc[i];
    }

    #pragma unroll
    for (int pc = 0; pc < 2; pc++) {
        const uint32_t wst = sb + QKV_WBASE + pc * QKV_WSTG;
        #pragma unroll
        for (int i = 0; i < 6; i++) {
            const int idx = tid + i * 256;
            const int row = idx >> 3;
            const int off = (idx & 7) * 16;
            cp16(wst + row * ROWB + off,         (const char*)g_whp + row * 2048 + pc * 128 + off);
            cp16(wst + 27648 + row * ROWB + off, (const char*)g_wlp + row * 2048 + pc * 128 + off);
        }
        asm volatile("cp.async.commit_group;" ::: "memory");
    }

    int stg = 0;
    for (int kci = 0; kci < 16; kci++) {
        if (kci < 15)
            asm volatile("cp.async.wait_group 1;" ::: "memory");
        else
            asm volatile("cp.async.wait_group 0;" ::: "memory");
        __syncthreads();

        if (kci + 2 < 16) {
            const int ps = stg + 2 >= 3 ? stg - 1 : stg + 2;
            const uint32_t wst = sb + QKV_WBASE + ps * QKV_WSTG;
            const int kb2 = (kci + 2) * 128;
            #pragma unroll
            for (int i = 0; i < 6; i++) {
                const int idx = tid + i * 256;
                const int row = idx >> 3;
                const int off = (idx & 7) * 16;
                cp16(wst + row * ROWB + off,         (const char*)g_whp + row * 2048 + kb2 + off);
                cp16(wst + 27648 + row * ROWB + off, (const char*)g_wlp + row * 2048 + kb2 + off);
            }
            asm volatile("cp.async.commit_group;" ::: "memory");
        }

        {
            uint32_t hp[16], lp[16];
            #pragma unroll
            for (int i = 0; i < 8; i++) {
                split2(xr[i].x, xr[i].y, hp[2*i],   lp[2*i]);
                split2(xr[i].z, xr[i].w, hp[2*i+1], lp[2*i+1]);
            }
            #pragma unroll
            for (int i = 0; i < 4; i++) {
                *(uint4*)(Xh + xob + 16*i) = make_uint4(hp[4*i], hp[4*i+1], hp[4*i+2], hp[4*i+3]);
                *(uint4*)(Xl + xob + 16*i) = make_uint4(lp[4*i], lp[4*i+1], lp[4*i+2], lp[4*i+3]);
            }
        }
        __syncwarp();

        if (kci + 1 < 16) {
            const float4* xsrc = (const float4*)&x[(size_t)(rowblk + xrow) * NE + (kci + 1) * 64 + xc0];
            #pragma unroll
            for (int i = 0; i < 8; i++) xr[i] = xsrc[i];
        }

        const uint32_t whb = sb + QKV_WBASE + stg * QKV_WSTG;
        const uint32_t wlb = whb + 27648;

        const int rb = (wid * 16 + g) * ROWB;
        #pragma unroll
        for (int ks = 0; ks < 4; ks++) {
            const int colb = ks * 32 + t3 * 4;
            uint32_t ah[4], al[4];
            ah[0] = *(uint32_t*)(Xh + rb + colb);
            ah[1] = *(uint32_t*)(Xh + rb + 8*ROWB + colb);
            ah[2] = *(uint32_t*)(Xh + rb + colb + 16);
            ah[3] = *(uint32_t*)(Xh + rb + 8*ROWB + colb + 16);
            al[0] = *(uint32_t*)(Xl + rb + colb);
            al[1] = *(uint32_t*)(Xl + rb + 8*ROWB + colb);
            al[2] = *(uint32_t*)(Xl + rb + colb + 16);
            al[3] = *(uint32_t*)(Xl + rb + 8*ROWB + colb + 16);
            #pragma unroll
            for (int ntp = 0; ntp < 12; ntp++) {
                uint32_t wh4[4], wl4[4];
                ldsm4(wh4, whb + lmw + ntp * (16 * ROWB) + ks * 32);
                ldsm4(wl4, wlb + lmw + ntp * (16 * ROWB) + ks * 32);
                mma16816(c[2*ntp],   ah, wh4[0], wh4[1]);
                mma16816(c[2*ntp],   ah, wl4[0], wl4[1]);
                mma16816(c[2*ntp],   al, wh4[0], wh4[1]);
                mma16816(c[2*ntp+1], ah, wh4[2], wh4[3]);
                mma16816(c[2*ntp+1], ah, wl4[2], wl4[3]);
                mma16816(c[2*ntp+1], al, wh4[2], wh4[3]);
            }
        }
        stg = (stg + 1 == 3) ? 0 : stg + 1;
    }

    const int r0 = rowblk + wid * 16 + g;
    #pragma unroll
    for (int nt = 0; nt < 8; nt++) {
        const int col = nt * 8 + t3 * 2;
        *(float2*)&g_q[(size_t)r0 * HS + col]       = make_float2(c[nt][0], c[nt][1]);
        *(float2*)&g_q[(size_t)(r0 + 8) * HS + col] = make_float2(c[nt][2], c[nt][3]);
    }
    #pragma unroll
    for (int nt = 8; nt < 16; nt++) {
        const int pidx = (nt - 8) * 4 + t3;
        uint32_t hi, lo;
        split2(c[nt][0], c[nt][1], hi, lo);
        g_khp[(size_t)r0 * 32 + pidx] = hi;
        g_klp[(size_t)r0 * 32 + pidx] = lo;
        split2(c[nt][2], c[nt][3], hi, lo);
        g_khp[(size_t)(r0 + 8) * 32 + pidx] = hi;
        g_klp[(size_t)(r0 + 8) * 32 + pidx] = lo;
    }

    __syncthreads();
    float* Vs = (float*)sm;
    const int rloc = wid * 16 + g;
    #pragma unroll
    for (int nt = 16; nt < 24; nt++) {
        const int n = nt * 8 + t3 * 2 - 128;
        Vs[n * 132 + rloc]           = c[nt][0];
        Vs[(n + 1) * 132 + rloc]     = c[nt][1];
        Vs[n * 132 + rloc + 8]       = c[nt][2];
        Vs[(n + 1) * 132 + rloc + 8] = c[nt][3];
    }
    __syncthreads();
    {
        const int d  = tid >> 2;
        const int cc = (tid & 3) * 32;
        const int bb = rowblk >> 12;
        const int t0 = rowblk & (NT - 1);
        uint32_t* dh = &g_vthp[((size_t)(bb * HS + d)) * 2048 + (t0 + cc) / 2];
        uint32_t* dl = &g_vtlp[((size_t)(bb * HS + d)) * 2048 + (t0 + cc) / 2];
        #pragma unroll
        for (int i = 0; i < 8; i++) {
            float4 v = *(float4*)&Vs[d * 132 + cc + 4*i];
            uint32_t h0, l0, h1, l1;
            split2(v.x, v.y, h0, l0);
            split2(v.z, v.w, h1, l1);
            dh[2*i] = h0;  dh[2*i+1] = h1;
            dl[2*i] = l0;  dl[2*i+1] = l1;
        }
    }
}

// ===========================================================================
// Stage 2: causal flash attention. 64-key tiles (proven), 3-stage ring,
// 1 full barrier + 1 pair-wise named barrier per iteration.
// Warps 0-3: keys 0-31; warps 4-7: keys 32-63. 16 rows/warp of 64-row Q tile.
// ===========================================================================
#define ATSTG 36864                 // stage: KH 9216 | KL 9216 | VH 9216 | VL 9216
#define AT_QHO (3 * ATSTG)          // 110592
#define AT_QLO (AT_QHO + 9216)
#define AT_MSO (AT_QLO + 9216)      // 129024, float2[2][64]
#define AT_SMEM (AT_MSO + 1024)     // 130048
#define OEXW 66

__global__ __launch_bounds__(256, 1) void attn4(float* __restrict__ o)
{
    extern __shared__ __align__(16) char sm[];
    const uint32_t sb = smem_u32(sm);
    const int tid  = threadIdx.x;
    const int wid  = tid >> 5;
    const int lane = tid & 31;
    const int g    = lane >> 2;
    const int t3   = lane & 3;
    const int wq   = wid & 3;
    const int side = wid >> 2;
    const int b    = blockIdx.y;

    const int m8 = lane >> 3;
    const int r8 = lane & 7;
    const uint32_t lmk = (uint32_t)((side * 32 + (m8 >> 1) * 8 + r8) * ROWB + (m8 & 1) * 16);
    const uint32_t lmv = (uint32_t)(((m8 >> 1) * 8 + r8) * ROWB + (m8 & 1) * 16 + side * 64);

    const char* khg = (const char*)g_khp + (size_t)b * NT * 128;
    const char* klg = (const char*)g_klp + (size_t)b * NT * 128;
    const char* vhg = (const char*)g_vthp + (size_t)b * HS * 8192;
    const char* vlg = (const char*)g_vtlp + (size_t)b * HS * 8192;

    const int pc_row = (tid * 2) >> 3;
    const int pc_off = ((tid * 2) & 7) * 16;

    for (int half = 0; half < 2; half++) {
        const int qt = half ? (63 - (int)blockIdx.x) : (int)blockIdx.x;
        const int nkt = qt + 1;
        const int qrow = b * NT + qt * 64;

        __syncthreads();   // prior half fully done (epilogue reads + cp drained)

        // ---- stage Q (scaled 1/8, split) into dedicated region ----
        {
            const int r  = tid >> 2;
            const int c0 = (tid & 3) * 16;
            const float4* src = (const float4*)&g_q[(size_t)(qrow + r) * HS + c0];
            uint32_t hp[8], lp[8];
            #pragma unroll
            for (int i = 0; i < 4; i++) {
                float4 v = src[i];
                split2(v.x * 0.125f, v.y * 0.125f, hp[2*i],   lp[2*i]);
                split2(v.z * 0.125f, v.w * 0.125f, hp[2*i+1], lp[2*i+1]);
            }
            const int ob = r * ROWB + c0 * 2;
            *(uint4*)(sm + AT_QHO + ob)      = make_uint4(hp[0], hp[1], hp[2], hp[3]);
            *(uint4*)(sm + AT_QHO + ob + 16) = make_uint4(hp[4], hp[5], hp[6], hp[7]);
            *(uint4*)(sm + AT_QLO + ob)      = make_uint4(lp[0], lp[1], lp[2], lp[3]);
            *(uint4*)(sm + AT_QLO + ob + 16) = make_uint4(lp[4], lp[5], lp[6], lp[7]);
        }
        __syncthreads();

        // ---- preload Q fragments (region never overwritten during loop) ----
        uint32_t qh[4][4], ql[4][4];
        {
            const int rb = (wq * 16 + g) * ROWB;
            #pragma unroll
            for (int ks = 0; ks < 4; ks++) {
                const int colb = ks * 32 + t3 * 4;
                qh[ks][0] = *(uint32_t*)(sm + AT_QHO + rb + colb);
                qh[ks][1] = *(uint32_t*)(sm + AT_QHO + rb + 8*ROWB + colb);
                qh[ks][2] = *(uint32_t*)(sm + AT_QHO + rb + colb + 16);
                qh[ks][3] = *(uint32_t*)(sm + AT_QHO + rb + 8*ROWB + colb + 16);
                ql[ks][0] = *(uint32_t*)(sm + AT_QLO + rb + colb);
                ql[ks][1] = *(uint32_t*)(sm + AT_QLO + rb + 8*ROWB + colb);
                ql[ks][2] = *(uint32_t*)(sm + AT_QLO + rb + colb + 16);
                ql[ks][3] = *(uint32_t*)(sm + AT_QLO + rb + 8*ROWB + colb + 16);
            }
        }

        float oacc[8][4];
        #pragma unroll
        for (int nt = 0; nt < 8; nt++)
            #pragma unroll
            for (int i = 0; i < 4; i++) oacc[nt][i] = 0.f;
        float mi0 = -1e30f, mi1 = -1e30f, li0 = 0.f, li1 = 0.f;

        // ---- prefetch tiles 0 and 1 ----
        #pragma unroll 1
        for (int pt = 0; pt < 2; pt++) {
            if (pt < nkt) {
                const uint32_t so = sb + pt * ATSTG + pc_row * ROWB + pc_off;
                const size_t ko = (size_t)(pt * 64 + pc_row) * 128 + pc_off;
                const size_t vo = (size_t)pc_row * 8192 + pt * 128 + pc_off;
                cp16(so,         khg + ko);  cp16(so + 16,         khg + ko + 16);
                cp16(so + 9216,  klg + ko);  cp16(so + 9216 + 16,  klg + ko + 16);
                cp16(so + 18432, vhg + vo);  cp16(so + 18432 + 16, vhg + vo + 16);
                cp16(so + 27648, vlg + vo);  cp16(so + 27648 + 16, vlg + vo + 16);
                asm volatile("cp.async.commit_group;" ::: "memory");
            }
        }

        int stg = 0;
        for (int kt = 0; kt < nkt; kt++) {
            if (kt + 1 < nkt)
                asm volatile("cp.async.wait_group 1;" ::: "memory");
            else
                asm volatile("cp.async.wait_group 0;" ::: "memory");
            __syncthreads();   // [A] stage kt visible; all warps done with stage (kt+2)%3

            // prefetch tile kt+2 into stage (stg+2)%3
            if (kt + 2 < nkt) {
                const int ps = stg + 2 >= 3 ? stg - 1 : stg + 2;
                const int t2 = kt + 2;
                const uint32_t so = sb + ps * ATSTG + pc_row * ROWB + pc_off;
                const size_t ko = (size_t)(t2 * 64 + pc_row) * 128 + pc_off;
                const size_t vo = (size_t)pc_row * 8192 + t2 * 128 + pc_off;
                cp16(so,         khg + ko);  cp16(so + 16,         khg + ko + 16);
                cp16(so + 9216,  klg + ko);  cp16(so + 9216 + 16,  klg + ko + 16);
                cp16(so + 18432, vhg + vo);  cp16(so + 18432 + 16, vhg + vo + 16);
                cp16(so + 27648, vlg + vo);  cp16(so + 27648 + 16, vlg + vo + 16);
                asm volatile("cp.async.commit_group;" ::: "memory");
            }

            const uint32_t khb = sb + stg * ATSTG;
            const uint32_t klb = khb + 9216;
            const uint32_t vhb = khb + 18432;
            const uint32_t vlb = khb + 27648;

            // ---- S = Q K^T (warp's 32 keys) ----
            float s[4][4];
            #pragma unroll
            for (int nt = 0; nt < 4; nt++)
                #pragma unroll
                for (int i = 0; i < 4; i++) s[nt][i] = 0.f;
            #pragma unroll
            for (int ks = 0; ks < 4; ks++) {
                uint32_t a4[4], b4[4], c4[4], d4[4];
                ldsm4(a4, khb + lmk + ks * 32);
                ldsm4(b4, khb + lmk + 16 * ROWB + ks * 32);
                ldsm4(c4, klb + lmk + ks * 32);
                ldsm4(d4, klb + lmk + 16 * ROWB + ks * 32);
                mma16816(s[0], qh[ks], a4[0], a4[1]);
                mma16816(s[0], qh[ks], c4[0], c4[1]);
                mma16816(s[0], ql[ks], a4[0], a4[1]);
                mma16816(s[1], qh[ks], a4[2], a4[3]);
                mma16816(s[1], qh[ks], c4[2], c4[3]);
                mma16816(s[1], ql[ks], a4[2], a4[3]);
                mma16816(s[2], qh[ks], b4[0], b4[1]);
                mma16816(s[2], qh[ks], d4[0], d4[1]);
                mma16816(s[2], ql[ks], b4[0], b4[1]);
                mma16816(s[3], qh[ks], b4[2], b4[3]);
                mma16816(s[3], qh[ks], d4[2], d4[3]);
                mma16816(s[3], ql[ks], b4[2], b4[3]);
            }

            if (kt == qt) {
                const int lr0 = wq * 16 + g;
                #pragma unroll
                for (int nt = 0; nt < 4; nt++) {
                    const int lc = side * 32 + nt * 8 + t3 * 2;
                    if (lc > lr0)         s[nt][0] = -1e30f;
                    if (lc + 1 > lr0)     s[nt][1] = -1e30f;
                    if (lc > lr0 + 8)     s[nt][2] = -1e30f;
                    if (lc + 1 > lr0 + 8) s[nt][3] = -1e30f;
                }
            }

            // ---- partial softmax over warp's 32 cols ----
            float m0 = -1e30f, m1 = -1e30f;
            #pragma unroll
            for (int nt = 0; nt < 4; nt++) {
                m0 = fmaxf(m0, fmaxf(s[nt][0], s[nt][1]));
                m1 = fmaxf(m1, fmaxf(s[nt][2], s[nt][3]));
            }
            m0 = fmaxf(m0, __shfl_xor_sync(0xffffffffu, m0, 1));
            m0 = fmaxf(m0, __shfl_xor_sync(0xffffffffu, m0, 2));
            m1 = fmaxf(m1, __shfl_xor_sync(0xffffffffu, m1, 1));
            m1 = fmaxf(m1, __shfl_xor_sync(0xffffffffu, m1, 2));

            float sum0 = 0.f, sum1 = 0.f;
            #pragma unroll
            for (int nt = 0; nt < 4; nt++) {
                s[nt][0] = __expf(s[nt][0] - m0);
                s[nt][1] = __expf(s[nt][1] - m0);
                s[nt][2] = __expf(s[nt][2] - m1);
                s[nt][3] = __expf(s[nt][3] - m1);
                sum0 += s[nt][0] + s[nt][1];
                sum1 += s[nt][2] + s[nt][3];
            }
            sum0 += __shfl_xor_sync(0xffffffffu, sum0, 1);
            sum0 += __shfl_xor_sync(0xffffffffu, sum0, 2);
            sum1 += __shfl_xor_sync(0xffffffffu, sum1, 1);
            sum1 += __shfl_xor_sync(0xffffffffu, sum1, 2);

            // ---- exchange (max, sum) with partner warp via named barrier ----
            if (t3 == 0) {
                *(float2*)(sm + AT_MSO + (side * 64 + wq * 16 + g) * 8)     = make_float2(m0, sum0);
                *(float2*)(sm + AT_MSO + (side * 64 + wq * 16 + g + 8) * 8) = make_float2(m1, sum1);
            }
            asm volatile("bar.sync %0, 64;" :: "r"(1 + wq) : "memory");   // [B] pair-wise
            const float2 ot0 = *(float2*)(sm + AT_MSO + ((1 - side) * 64 + wq * 16 + g) * 8);
            const float2 ot1 = *(float2*)(sm + AT_MSO + ((1 - side) * 64 + wq * 16 + g + 8) * 8);

            const float mn0 = fmaxf(mi0, fmaxf(m0, ot0.x));
            const float mn1 = fmaxf(mi1, fmaxf(m1, ot1.x));
            const float fo0 = __expf(m0 - mn0), fo1 = __expf(m1 - mn1);
            const float corr0 = __expf(mi0 - mn0), corr1 = __expf(mi1 - mn1);
            li0 = li0 * corr0 + sum0 * fo0 + ot0.y * __expf(ot0.x - mn0);
            li1 = li1 * corr1 + sum1 * fo1 + ot1.y * __expf(ot1.x - mn1);
            mi0 = mn0;  mi1 = mn1;

            #pragma unroll
            for (int nt = 0; nt < 4; nt++) {
                s[nt][0] *= fo0;  s[nt][1] *= fo0;
                s[nt][2] *= fo1;  s[nt][3] *= fo1;
            }
            #pragma unroll
            for (int nt = 0; nt < 8; nt++) {
                oacc[nt][0] *= corr0;  oacc[nt][1] *= corr0;
                oacc[nt][2] *= corr1;  oacc[nt][3] *= corr1;
            }

            // ---- O += P V ----
            #pragma unroll
            for (int k2 = 0; k2 < 2; k2++) {
                uint32_t pah[4], pal[4];
                split2(s[2*k2][0],   s[2*k2][1],   pah[0], pal[0]);
                split2(s[2*k2][2],   s[2*k2][3],   pah[1], pal[1]);
                split2(s[2*k2+1][0], s[2*k2+1][1], pah[2], pal[2]);
                split2(s[2*k2+1][2], s[2*k2+1][3], pah[3], pal[3]);
                #pragma unroll
                for (int dt = 0; dt < 4; dt++) {
                    uint32_t vh4[4], vl4[4];
                    ldsm4(vh4, vhb + dt * (16 * ROWB) + lmv + k2 * 32);
                    ldsm4(vl4, vlb + dt * (16 * ROWB) + lmv + k2 * 32);
                    mma16816(oacc[2*dt],   pah, vh4[0], vh4[1]);
                    mma16816(oacc[2*dt],   pah, vl4[0], vl4[1]);
                    mma16816(oacc[2*dt],   pal, vh4[0], vh4[1]);
                    mma16816(oacc[2*dt+1], pah, vh4[2], vh4[3]);
                    mma16816(oacc[2*dt+1], pah, vl4[2], vl4[3]);
                    mma16816(oacc[2*dt+1], pal, vh4[2], vh4[3]);
                }
            }
            stg = (stg + 1 == 3) ? 0 : stg + 1;
        }

        // ---- epilogue: merge O partials ----
        __syncthreads();
        float* Oex = (float*)sm;   // stage 0 area, pipeline drained
        if (side == 1) {
            #pragma unroll
            for (int nt = 0; nt < 8; nt++) {
                const int col = nt * 8 + t3 * 2;
                Oex[(wq*16 + g) * OEXW + col]         = oacc[nt][0];
                Oex[(wq*16 + g) * OEXW + col + 1]     = oacc[nt][1];
                Oex[(wq*16 + g + 8) * OEXW + col]     = oacc[nt][2];
                Oex[(wq*16 + g + 8) * OEXW + col + 1] = oacc[nt][3];
            }
        }
        __syncthreads();
        if (side == 0) {
            const float inv0 = 1.0f / li0;
            const float inv1 = 1.0f / li1;
            const int rowA = qrow + wq * 16 + g;
            #pragma unroll
            for (int nt = 0; nt < 8; nt++) {
                const int col = nt * 8 + t3 * 2;
                float a0 = (oacc[nt][0] + Oex[(wq*16 + g) * OEXW + col])     * inv0;
                float a1 = (oacc[nt][1] + Oex[(wq*16 + g) * OEXW + col + 1]) * inv0;
                float a2 = (oacc[nt][2] + Oex[(wq*16 + g + 8) * OEXW + col])     * inv1;
                float a3 = (oacc[nt][3] + Oex[(wq*16 + g + 8) * OEXW + col + 1]) * inv1;
                *(float2*)&o[(size_t)rowA * HS + col]       = make_float2(a0, a1);
                *(float2*)&o[(size_t)(rowA + 8) * HS + col] = make_float2(a2, a3);
            }
        }
    }
}

// ===========================================================================
extern "C" void kernel_launch(void* const* d_in, const int* in_sizes, int n_in,
                              void* d_out, int out_size)
{
    const float* x  = (const float*)d_in[0];
    const float* Wq = (const float*)d_in[1];
    const float* Wk = (const float*)d_in[2];
    const float* Wv = (const float*)d_in[3];
    float* out = (float*)d_out;
    (void)in_sizes; (void)n_in; (void)out_size;

    wprep<<<192, 256>>>(Wq, Wk, Wv);

    cudaFuncSetAttribute(qkv_mma, cudaFuncAttributeMaxDynamicSharedMemorySize,
                         QKV_SMEM);
    qkv_mma<<<128, 256, QKV_SMEM>>>(x, Wq, Wk, Wv);

    cudaFuncSetAttribute(attn4, cudaFuncAttributeMaxDynamicSharedMemorySize,
                         AT_SMEM);
    attn4<<<dim3(32, NB), 256, AT_SMEM>>>(out);
}